// round 6
// baseline (speedup 1.0000x reference)
#include <cuda_runtime.h>
#include <cuda_bf16.h>
#include <cstdint>

#define NN 50000
#define NE 800000
#define ET 850000   // NE + NN self loops
#define NG 100
#define C1 256      // heads*hid = 4*64
#define H1 4
#define CH1 64
#define C2 128
#define NEG_SLOPE 0.2f
#define EPSV 1e-16f

// ---------------- scratch (device globals; no allocation allowed) ----------------
__device__ __align__(16) float g_h1[NN * C1];     // x @ W1
__device__ __align__(16) float g_out1[NN * C1];   // layer-1 aggregated (then finalized in place)
__device__ __align__(16) float g_h2[NN * C2];     // relu(out1) @ W2
__device__ __align__(16) float g_out2[NN * C2];   // layer-2 aggregated
__device__ __align__(16) float g_asrc1[NN * H1];
__device__ __align__(16) float g_adst1[NN * H1];
__device__ unsigned g_amax1[NN * H1];
__device__ float g_denom1[NN * H1];
__device__ float g_asrc2[NN], g_adst2[NN];
__device__ unsigned g_amax2[NN];
__device__ float g_denom2[NN];
__device__ float g_cnt[NG];

// ---------------- helpers ----------------
__device__ __forceinline__ unsigned fenc(float f) {
    unsigned u = __float_as_uint(f);
    return (u & 0x80000000u) ? ~u : (u | 0x80000000u);
}
__device__ __forceinline__ float fdec(unsigned u) {
    return (u & 0x80000000u) ? __uint_as_float(u & 0x7fffffffu) : __uint_as_float(~u);
}
__device__ __forceinline__ float lrelu(float a) { return a > 0.f ? a : NEG_SLOPE * a; }

// ---------------- init: zero all accumulators ----------------
__global__ void init_kernel(float* __restrict__ pool) {
    int i = blockIdx.x * blockDim.x + threadIdx.x;
    if (i < NN * C1) g_out1[i] = 0.f;
    if (i < NN * C2) g_out2[i] = 0.f;
    if (i < NN * H1) { g_denom1[i] = 0.f; g_amax1[i] = 0u; }
    if (i < NN)      { g_denom2[i] = 0.f; g_amax2[i] = 0u; }
    if (i < NG * C2) pool[i] = 0.f;
    if (i < NG)      g_cnt[i] = 0.f;
}

// ---------------- SGEMM: C[M,N] = A[M,K] @ B[K,N], row-major, fp32 ----------------
// BM=64 BN=64 BK=16, 256 threads, 4x4 per thread. N,K multiples of 64/16; M guarded.
__global__ __launch_bounds__(256) void sgemm_kernel(
    const float* __restrict__ A, const float* __restrict__ B, float* __restrict__ C,
    int M, int N, int K)
{
    __shared__ float As[16][64];
    __shared__ float Bs[16][64];
    const int bm = blockIdx.y * 64;
    const int bn = blockIdx.x * 64;
    const int t = threadIdx.x;
    const int tx = t & 15, ty = t >> 4;
    const int arow = t >> 2, ac = (t & 3) * 4;
    const int brow = t >> 4, bc = (t & 15) * 4;

    float acc[4][4] = {};
    for (int k0 = 0; k0 < K; k0 += 16) {
        float4 av = make_float4(0.f, 0.f, 0.f, 0.f);
        if (bm + arow < M)
            av = *(const float4*)(A + (size_t)(bm + arow) * K + k0 + ac);
        As[ac + 0][arow] = av.x; As[ac + 1][arow] = av.y;
        As[ac + 2][arow] = av.z; As[ac + 3][arow] = av.w;
        *(float4*)&Bs[brow][bc] = *(const float4*)(B + (size_t)(k0 + brow) * N + bn + bc);
        __syncthreads();
#pragma unroll
        for (int k = 0; k < 16; k++) {
            float a0 = As[k][ty * 4 + 0], a1 = As[k][ty * 4 + 1];
            float a2 = As[k][ty * 4 + 2], a3 = As[k][ty * 4 + 3];
            float b0 = Bs[k][tx * 4 + 0], b1 = Bs[k][tx * 4 + 1];
            float b2 = Bs[k][tx * 4 + 2], b3 = Bs[k][tx * 4 + 3];
            acc[0][0] += a0 * b0; acc[0][1] += a0 * b1; acc[0][2] += a0 * b2; acc[0][3] += a0 * b3;
            acc[1][0] += a1 * b0; acc[1][1] += a1 * b1; acc[1][2] += a1 * b2; acc[1][3] += a1 * b3;
            acc[2][0] += a2 * b0; acc[2][1] += a2 * b1; acc[2][2] += a2 * b2; acc[2][3] += a2 * b3;
            acc[3][0] += a3 * b0; acc[3][1] += a3 * b1; acc[3][2] += a3 * b2; acc[3][3] += a3 * b3;
        }
        __syncthreads();
    }
#pragma unroll
    for (int i = 0; i < 4; i++) {
        int row = bm + ty * 4 + i;
        if (row < M) {
            float4 v = make_float4(acc[i][0], acc[i][1], acc[i][2], acc[i][3]);
            *(float4*)(C + (size_t)row * N + bn + tx * 4) = v;
        }
    }
}

// ---------------- attention scores: a_src[n,h] = <h[n,h,:], att_src[h,:]> ----------------
__global__ void attn_scores_kernel(const float* __restrict__ h,
                                   const float* __restrict__ att_s,
                                   const float* __restrict__ att_d,
                                   float* __restrict__ asrc, float* __restrict__ adst,
                                   int heads, int ch)
{
    int i = blockIdx.x * blockDim.x + threadIdx.x;
    if (i >= NN * heads) return;
    int node = i / heads, hd = i - node * heads;
    const float4* hp = (const float4*)(h + (size_t)node * heads * ch + hd * ch);
    const float4* sp = (const float4*)(att_s + hd * ch);
    const float4* dp = (const float4*)(att_d + hd * ch);
    float s = 0.f, d = 0.f;
    for (int c = 0; c < ch / 4; c++) {
        float4 v = hp[c], a = sp[c], b = dp[c];
        s += v.x * a.x + v.y * a.y + v.z * a.z + v.w * a.w;
        d += v.x * b.x + v.y * b.y + v.z * b.z + v.w * b.w;
    }
    asrc[i] = s; adst[i] = d;
}

// ---------------- edge pass 1: segment max of leaky_relu(alpha), H=4 (float4 path) ----------------
__global__ void edge_max4_kernel(const int* __restrict__ ei,
                                 const float* __restrict__ asrc, const float* __restrict__ adst,
                                 unsigned* __restrict__ amax)
{
    int e = blockIdx.x * blockDim.x + threadIdx.x;
    if (e >= ET) return;
    int s, dn;
    if (e < NE) { s = ei[e]; dn = ei[NE + e]; }
    else        { s = dn = e - NE; }
    float4 av = *(const float4*)(asrc + (size_t)s * 4);
    float4 dv = *(const float4*)(adst + (size_t)dn * 4);
    unsigned* ap = amax + (size_t)dn * 4;
    atomicMax(ap + 0, fenc(lrelu(av.x + dv.x)));
    atomicMax(ap + 1, fenc(lrelu(av.y + dv.y)));
    atomicMax(ap + 2, fenc(lrelu(av.z + dv.z)));
    atomicMax(ap + 3, fenc(lrelu(av.w + dv.w)));
}

// ---------------- edge pass 1 (H=1) ----------------
__global__ void edge_max1_kernel(const int* __restrict__ ei,
                                 const float* __restrict__ asrc, const float* __restrict__ adst,
                                 unsigned* __restrict__ amax)
{
    int e = blockIdx.x * blockDim.x + threadIdx.x;
    if (e >= ET) return;
    int s, dn;
    if (e < NE) { s = ei[e]; dn = ei[NE + e]; }
    else        { s = dn = e - NE; }
    atomicMax(&amax[dn], fenc(lrelu(asrc[s] + adst[dn])));
}

// ---------------- edge pass 2: e=exp(alpha-amax); denom += e; out[dst] += h[src]*e ----------------
// One warp per edge. C channels split over 32 lanes (CPL = C/32 each, float4 chunks).
template <int H, int C>
__global__ __launch_bounds__(256) void edge_accum_kernel(
    const int* __restrict__ ei,
    const float* __restrict__ h,
    const float* __restrict__ asrc, const float* __restrict__ adst,
    const unsigned* __restrict__ amax,
    float* __restrict__ denom, float* __restrict__ out)
{
    int warp = (blockIdx.x * blockDim.x + threadIdx.x) >> 5;
    int lane = threadIdx.x & 31;
    if (warp >= ET) return;
    int s, dn;
    if (warp < NE) { s = ei[warp]; dn = ei[NE + warp]; }
    else           { s = dn = warp - NE; }

    constexpr int CPL = C / 32;          // channels per lane
    constexpr int CH  = C / H;           // channels per head
    const int hd = (lane * CPL) / CH;    // head owning this lane's channels

    float a = lrelu(asrc[s * H + hd] + adst[dn * H + hd]);
    float e = __expf(a - fdec(amax[dn * H + hd]));

    if ((lane % (32 / H)) == 0) atomicAdd(&denom[dn * H + hd], e);

    const float4* hp = (const float4*)(h + (size_t)s * C);
    float* op = out + (size_t)dn * C + lane * CPL;
#pragma unroll
    for (int j = 0; j < CPL / 4; j++) {
        float4 v = hp[lane * (CPL / 4) + j];
        v.x *= e; v.y *= e; v.z *= e; v.w *= e;
        asm volatile("red.global.add.v4.f32 [%0], {%1,%2,%3,%4};"
                     :: "l"(op + j * 4), "f"(v.x), "f"(v.y), "f"(v.z), "f"(v.w)
                     : "memory");
    }
}

// ---------------- layer-1 finalize: out = relu(out/(denom+eps) + bias) ----------------
__global__ void finalize1_kernel(const float* __restrict__ bias) {
    int i = blockIdx.x * blockDim.x + threadIdx.x;
    if (i >= NN * C1) return;
    int n = i >> 8, c = i & 255, hd = c >> 6;
    float v = g_out1[i] / (g_denom1[n * H1 + hd] + EPSV) + bias[c];
    g_out1[i] = v > 0.f ? v : 0.f;
}

// ---------------- layer-2 finalize + pooled sum ----------------
__global__ void finalize2_pool_kernel(const float* __restrict__ bias,
                                      const int* __restrict__ batch,
                                      float* __restrict__ pool) {
    int i = blockIdx.x * blockDim.x + threadIdx.x;
    if (i >= NN * C2) return;
    int n = i >> 7, c = i & 127;
    float v = g_out2[i] / (g_denom2[n] + EPSV) + bias[c];
    v = v > 0.f ? v : 0.f;
    int g = batch[n];
    atomicAdd(&pool[g * C2 + c], v);
    if (c == 0) atomicAdd(&g_cnt[g], 1.0f);
}

__global__ void pool_div_kernel(float* __restrict__ pool) {
    int i = blockIdx.x * blockDim.x + threadIdx.x;
    if (i >= NG * C2) return;
    int g = i >> 7;
    float c = g_cnt[g];
    pool[i] = pool[i] / (c > 1.f ? c : 1.f);
}

// ---------------- host launcher (graph-capturable, default stream) ----------------
extern "C" void kernel_launch(void* const* d_in, const int* in_sizes, int n_in,
                              void* d_out, int out_size)
{
    const float* x    = (const float*)d_in[0];
    const float* W1   = (const float*)d_in[1];
    const float* as1  = (const float*)d_in[2];
    const float* ad1  = (const float*)d_in[3];
    const float* b1   = (const float*)d_in[4];
    const float* W2   = (const float*)d_in[5];
    const float* as2  = (const float*)d_in[6];
    const float* ad2  = (const float*)d_in[7];
    const float* b2   = (const float*)d_in[8];
    const int*   ei   = (const int*)d_in[9];     // int32 (jax x64 disabled)
    const int*   batch= (const int*)d_in[10];    // int32
    float* pool = (float*)d_out;

    float *p_h1, *p_out1, *p_h2, *p_out2;
    float *p_asrc1, *p_adst1, *p_denom1, *p_asrc2, *p_adst2, *p_denom2;
    unsigned *p_amax1, *p_amax2;
    cudaGetSymbolAddress((void**)&p_h1, g_h1);
    cudaGetSymbolAddress((void**)&p_out1, g_out1);
    cudaGetSymbolAddress((void**)&p_h2, g_h2);
    cudaGetSymbolAddress((void**)&p_out2, g_out2);
    cudaGetSymbolAddress((void**)&p_asrc1, g_asrc1);
    cudaGetSymbolAddress((void**)&p_adst1, g_adst1);
    cudaGetSymbolAddress((void**)&p_amax1, g_amax1);
    cudaGetSymbolAddress((void**)&p_denom1, g_denom1);
    cudaGetSymbolAddress((void**)&p_asrc2, g_asrc2);
    cudaGetSymbolAddress((void**)&p_adst2, g_adst2);
    cudaGetSymbolAddress((void**)&p_amax2, g_amax2);
    cudaGetSymbolAddress((void**)&p_denom2, g_denom2);

    const int TB = 256;

    // 0) init accumulators + output
    init_kernel<<<(NN * C1 + TB - 1) / TB, TB>>>(pool);

    // 1) h1 = x @ W1   (50000x256x256)
    {
        dim3 grid(C1 / 64, (NN + 63) / 64);
        sgemm_kernel<<<grid, 256>>>(x, W1, p_h1, NN, C1, 256);
    }
    // 2) attention scores layer 1
    attn_scores_kernel<<<(NN * H1 + TB - 1) / TB, TB>>>(p_h1, as1, ad1, p_asrc1, p_adst1, H1, CH1);
    // 3) segment max (vectorized H=4 path)
    edge_max4_kernel<<<(ET + TB - 1) / TB, TB>>>(ei, p_asrc1, p_adst1, p_amax1);
    // 4) exp + denom + message accumulate (warp per edge)
    {
        long long threads = (long long)ET * 32;
        edge_accum_kernel<H1, C1><<<(unsigned)((threads + TB - 1) / TB), TB>>>(
            ei, p_h1, p_asrc1, p_adst1, p_amax1, p_denom1, p_out1);
    }
    // 5) finalize layer 1 (normalize + bias + relu) in place
    finalize1_kernel<<<(NN * C1 + TB - 1) / TB, TB>>>(b1);

    // 6) h2 = relu_out1 @ W2   (50000x256x128)
    {
        dim3 grid(C2 / 64, (NN + 63) / 64);
        sgemm_kernel<<<grid, 256>>>(p_out1, W2, p_h2, NN, C2, 256);
    }
    // 7) attention scores layer 2 (1 head, 128 ch)
    attn_scores_kernel<<<(NN + TB - 1) / TB, TB>>>(p_h2, as2, ad2, p_asrc2, p_adst2, 1, C2);
    // 8) segment max layer 2
    edge_max1_kernel<<<(ET + TB - 1) / TB, TB>>>(ei, p_asrc2, p_adst2, p_amax2);
    // 9) accumulate layer 2
    {
        long long threads = (long long)ET * 32;
        edge_accum_kernel<1, C2><<<(unsigned)((threads + TB - 1) / TB), TB>>>(
            ei, p_h2, p_asrc2, p_adst2, p_amax2, p_denom2, p_out2);
    }
    // 10) finalize layer 2 + pooled sums
    finalize2_pool_kernel<<<(NN * C2 + TB - 1) / TB, TB>>>(b2, batch, pool);
    // 11) mean
    pool_div_kernel<<<(NG * C2 + TB - 1) / TB, TB>>>(pool);
}